// round 14
// baseline (speedup 1.0000x reference)
#include <cuda_runtime.h>
#include <cuda_fp16.h>
#include <cstdint>

#define Nn   40000
#define Ee   640000
#define INF  128
#define HIDF 256
#define CLSF 40
#define MTILES 313
#define MPAD  (MTILES * 128)     // 40064
#define SBLK  157                // ceil(40000/256)
#define W2N   48                 // padded n for W2^T
#define W2LD  264                // padded k stride (528B rows)

// ---- scratch (device globals; zero-initialized at load) ----
__device__ int    g_deg[Nn];
__device__ int    g_row[Nn + 1];
__device__ int    g_cur[Nn];
__device__ int    g_esrc[Ee];
__device__ int    g_bsum[SBLK];
__device__ int    g_boff[SBLK];
__device__ float  g_norm[Nn];
__device__ float  g_norm2[Nn];
__device__ int    g_barc;                 // grid-barrier arrival count
__device__ volatile int g_barg;           // grid-barrier generation
__device__ __align__(16) __half g_Xs[Nn * INF];             // norm.*X fp16
__device__ __align__(16) __half g_T[Nn * INF];              // norm2.*(A Xs) fp16
__device__ __align__(16) __half g_Ah[MPAD * INF];           // norm.*(A T) fp16, pad rows 0
__device__ __align__(16) unsigned short g_Bh[HIDF * INF];   // W1^T fp16, [n][k]
__device__ __align__(16) unsigned short g_W2h[W2N * W2LD];  // W2^T fp16
__device__ float  g_part[4][Nn * CLSF];                     // gemm2 partials

// ---------------- init: zero deg + weight prep (fp16 single) ----------------
__global__ void init_k(const float* __restrict__ W1, const float* __restrict__ W2) {
    int t = blockIdx.x * 256 + threadIdx.x;
    if (t < Nn) g_deg[t] = 0;
    if (t < 8192) {                         // W1: n = t>>5 (256), k0 = (t&31)*4
        int n = t >> 5, k0 = (t & 31) * 4;
        unsigned short h[4];
#pragma unroll
        for (int i = 0; i < 4; i++)
            h[i] = __half_as_ushort(__float2half_rn(W1[(k0 + i) * HIDF + n]));
        *(uint2*)&g_Bh[n * INF + k0] =
            make_uint2((uint32_t)h[1] << 16 | h[0], (uint32_t)h[3] << 16 | h[2]);
    } else if (t < 8192 + 2560) {           // W2: n = u>>6 (40), k0 = (u&63)*4
        int u = t - 8192;
        int n = u >> 6, k0 = (u & 63) * 4;
        unsigned short h[4];
#pragma unroll
        for (int i = 0; i < 4; i++)
            h[i] = __half_as_ushort(__float2half_rn(W2[(k0 + i) * CLSF + n]));
        *(uint2*)&g_W2h[n * W2LD + k0] =
            make_uint2((uint32_t)h[1] << 16 | h[0], (uint32_t)h[3] << 16 | h[2]);
    }
}

// ---- histogram: 4 edges/thread, exact grid ----
__global__ void hist_k(const int4* __restrict__ dst4) {
    int i = blockIdx.x * 256 + threadIdx.x;      // < 160000 exact
    int4 d = dst4[i];
    atomicAdd(&g_deg[d.x], 1);
    atomicAdd(&g_deg[d.y], 1);
    atomicAdd(&g_deg[d.z], 1);
    atomicAdd(&g_deg[d.w], 1);
}

// ---- software grid barrier (all SBLK blocks resident by construction) ----
__device__ __forceinline__ void gridbar() {
    __threadfence();
    __syncthreads();
    if (threadIdx.x == 0) {
        int gen = g_barg;
        if (atomicAdd(&g_barc, 1) == SBLK - 1) {
            g_barc = 0;
            __threadfence();
            g_barg = gen + 1;
        } else {
            while (g_barg == gen) { }
        }
    }
    __syncthreads();
}

// ---- fused CSR build: bsum | bar | bscan | bar | fill + prepX ----
__global__ void __launch_bounds__(256) csr_k(const float4* __restrict__ xin) {
    __shared__ int ws[8];
    __shared__ float snorm[256];
    int tid = threadIdx.x, b = blockIdx.x;
    int lane = tid & 31, w = tid >> 5;
    int i = b * 256 + tid;

    // phase 1: per-block degree sums
    int d = (i < Nn) ? g_deg[i] : 0;
    {
        int v = d;
#pragma unroll
        for (int o = 16; o > 0; o >>= 1) v += __shfl_down_sync(0xffffffffu, v, o);
        if (lane == 0) ws[w] = v;
        __syncthreads();
        if (w == 0) {
            int s = (lane < 8) ? ws[lane] : 0;
#pragma unroll
            for (int o = 4; o > 0; o >>= 1) s += __shfl_down_sync(0xffffffffu, s, o);
            if (lane == 0) g_bsum[b] = s;
        }
    }
    gridbar();

    // phase 2: block 0 scans the 157 block sums
    if (b == 0) {
        int v = (tid < SBLK) ? g_bsum[tid] : 0;
        int inc = v;
#pragma unroll
        for (int o = 1; o < 32; o <<= 1) {
            int n = __shfl_up_sync(0xffffffffu, inc, o);
            if (lane >= o) inc += n;
        }
        if (lane == 31) ws[w] = inc;
        __syncthreads();
        if (w == 0) {
            int s = (lane < 8) ? ws[lane] : 0;
            int si = s;
#pragma unroll
            for (int o = 1; o < 8; o <<= 1) {
                int n = __shfl_up_sync(0xffffffffu, si, o);
                if (lane >= o) si += n;
            }
            if (lane < 8) ws[lane] = si - s;
        }
        __syncthreads();
        if (tid < SBLK) g_boff[tid] = ws[w] + inc - v;
    }
    gridbar();

    // phase 3: local exclusive scan -> row/cur/norm
    {
        int inc = d;
#pragma unroll
        for (int o = 1; o < 32; o <<= 1) {
            int n = __shfl_up_sync(0xffffffffu, inc, o);
            if (lane >= o) inc += n;
        }
        if (lane == 31) ws[w] = inc;
        __syncthreads();
        if (w == 0) {
            int s = (lane < 8) ? ws[lane] : 0;
            int si = s;
#pragma unroll
            for (int o = 1; o < 8; o <<= 1) {
                int n = __shfl_up_sync(0xffffffffu, si, o);
                if (lane >= o) si += n;
            }
            if (lane < 8) ws[lane] = si - s;
        }
        __syncthreads();
        float nm = 0.f;
        if (i < Nn) {
            int off = g_boff[b] + ws[w] + inc - d;
            g_row[i] = off;
            g_cur[i] = off;
            nm = rsqrtf(fmaxf((float)d, 1.0f));
            g_norm[i] = nm;
            g_norm2[i] = nm * nm;
        }
        snorm[tid] = nm;
    }
    __syncthreads();

    // phase 3.5: prepX for this block's 256 nodes (warp-coalesced rows)
    {
        int base = b * 256;
        for (int j = tid; j < 256 * 32; j += 256) {
            int ln = j >> 5, c = j & 31;
            int node = base + ln;
            if (node < Nn) {
                float nm = snorm[ln];
                float4 x = xin[node * 32 + c];
                __half2 p0 = __floats2half2_rn(x.x * nm, x.y * nm);
                __half2 p1 = __floats2half2_rn(x.z * nm, x.w * nm);
                uint2 pk;
                pk.x = *(uint32_t*)&p0;
                pk.y = *(uint32_t*)&p1;
                ((uint2*)g_Xs)[node * 32 + c] = pk;
            }
        }
    }
}

// ---- permute: 4 edges/thread ----
__global__ void permute_k(const int4* __restrict__ src4, const int4* __restrict__ dst4) {
    int i = blockIdx.x * 256 + threadIdx.x;      // < 160000 exact
    int4 s = src4[i];
    int4 dd = dst4[i];
    int p;
    p = atomicAdd(&g_cur[dd.x], 1); g_esrc[p] = s.x;
    p = atomicAdd(&g_cur[dd.y], 1); g_esrc[p] = s.y;
    p = atomicAdd(&g_cur[dd.z], 1); g_esrc[p] = s.z;
    p = atomicAdd(&g_cur[dd.w], 1); g_esrc[p] = s.w;
}

// ---- hop1: T[v] = norm2[v] * sum Xs[src] ----
__global__ void gather1_k() {
    int w = (blockIdx.x * blockDim.x + threadIdx.x) >> 5;
    int lane = threadIdx.x & 31;
    if (w >= Nn) return;
    int beg = g_row[w], end = beg + g_deg[w];
    const uint2* rows = (const uint2*)g_Xs;
    float a0 = 0.f, a1 = 0.f, a2 = 0.f, a3 = 0.f;
    int e = beg;
    for (; e + 3 < end; e += 4) {
        int s0 = g_esrc[e], s1 = g_esrc[e + 1], s2 = g_esrc[e + 2], s3 = g_esrc[e + 3];
        uint2 p0 = rows[s0 * 32 + lane], p1 = rows[s1 * 32 + lane];
        uint2 p2 = rows[s2 * 32 + lane], p3 = rows[s3 * 32 + lane];
        float2 f;
        f = __half22float2(*(__half2*)&p0.x); a0 += f.x; a1 += f.y;
        f = __half22float2(*(__half2*)&p0.y); a2 += f.x; a3 += f.y;
        f = __half22float2(*(__half2*)&p1.x); a0 += f.x; a1 += f.y;
        f = __half22float2(*(__half2*)&p1.y); a2 += f.x; a3 += f.y;
        f = __half22float2(*(__half2*)&p2.x); a0 += f.x; a1 += f.y;
        f = __half22float2(*(__half2*)&p2.y); a2 += f.x; a3 += f.y;
        f = __half22float2(*(__half2*)&p3.x); a0 += f.x; a1 += f.y;
        f = __half22float2(*(__half2*)&p3.y); a2 += f.x; a3 += f.y;
    }
    for (; e < end; e++) {
        int s0 = g_esrc[e];
        uint2 p0 = rows[s0 * 32 + lane];
        float2 f;
        f = __half22float2(*(__half2*)&p0.x); a0 += f.x; a1 += f.y;
        f = __half22float2(*(__half2*)&p0.y); a2 += f.x; a3 += f.y;
    }
    float n2 = g_norm2[w];
    __half2 q0 = __floats2half2_rn(a0 * n2, a1 * n2);
    __half2 q1 = __floats2half2_rn(a2 * n2, a3 * n2);
    uint2 o;
    o.x = *(uint32_t*)&q0;
    o.y = *(uint32_t*)&q1;
    ((uint2*)g_T)[w * 32 + lane] = o;
}

// ---- hop2: Ah[v] = norm[v] * sum T[src] ----
__global__ void gather2_k() {
    int w = (blockIdx.x * blockDim.x + threadIdx.x) >> 5;
    int lane = threadIdx.x & 31;
    if (w >= Nn) return;
    int beg = g_row[w], end = beg + g_deg[w];
    const uint2* rows = (const uint2*)g_T;
    float a0 = 0.f, a1 = 0.f, a2 = 0.f, a3 = 0.f;
    int e = beg;
    for (; e + 3 < end; e += 4) {
        int s0 = g_esrc[e], s1 = g_esrc[e + 1], s2 = g_esrc[e + 2], s3 = g_esrc[e + 3];
        uint2 p0 = rows[s0 * 32 + lane], p1 = rows[s1 * 32 + lane];
        uint2 p2 = rows[s2 * 32 + lane], p3 = rows[s3 * 32 + lane];
        float2 f;
        f = __half22float2(*(__half2*)&p0.x); a0 += f.x; a1 += f.y;
        f = __half22float2(*(__half2*)&p0.y); a2 += f.x; a3 += f.y;
        f = __half22float2(*(__half2*)&p1.x); a0 += f.x; a1 += f.y;
        f = __half22float2(*(__half2*)&p1.y); a2 += f.x; a3 += f.y;
        f = __half22float2(*(__half2*)&p2.x); a0 += f.x; a1 += f.y;
        f = __half22float2(*(__half2*)&p2.y); a2 += f.x; a3 += f.y;
        f = __half22float2(*(__half2*)&p3.x); a0 += f.x; a1 += f.y;
        f = __half22float2(*(__half2*)&p3.y); a2 += f.x; a3 += f.y;
    }
    for (; e < end; e++) {
        int s0 = g_esrc[e];
        uint2 p0 = rows[s0 * 32 + lane];
        float2 f;
        f = __half22float2(*(__half2*)&p0.x); a0 += f.x; a1 += f.y;
        f = __half22float2(*(__half2*)&p0.y); a2 += f.x; a3 += f.y;
    }
    float nw = g_norm[w];
    __half2 q0 = __floats2half2_rn(a0 * nw, a1 * nw);
    __half2 q1 = __floats2half2_rn(a2 * nw, a3 * nw);
    uint2 o;
    o.x = *(uint32_t*)&q0;
    o.y = *(uint32_t*)&q1;
    ((uint2*)g_Ah)[w * 32 + lane] = o;
}

// ---------------- fused GEMM1+GEMM2 via fp16 mma.sync (1-pass) ----------------
#define SA   0                   // 128 x 272B = 34816
#define SB   34816               // 128 x 272B = 34816
#define SW2  69632               // 48*264*2 = 25344
#define SM_TOT 94976

__device__ __forceinline__ uint32_t smem_u32(const void* p) {
    uint32_t a;
    asm("{ .reg .u64 t; cvta.to.shared.u64 t, %1; cvt.u32.u64 %0, t; }" : "=r"(a) : "l"(p));
    return a;
}
#define LDSM4(R, addr) \
    asm volatile("ldmatrix.sync.aligned.m8n8.x4.shared.b16 {%0,%1,%2,%3}, [%4];" \
        : "=r"((R)[0]), "=r"((R)[1]), "=r"((R)[2]), "=r"((R)[3]) : "r"(addr))
#define MMAF16(C, A, B0, B1) \
    asm volatile("mma.sync.aligned.m16n8k16.row.col.f32.f16.f16.f32 " \
        "{%0,%1,%2,%3},{%4,%5,%6,%7},{%8,%9},{%0,%1,%2,%3};" \
        : "+f"((C)[0]), "+f"((C)[1]), "+f"((C)[2]), "+f"((C)[3]) \
        : "r"((A)[0]), "r"((A)[1]), "r"((A)[2]), "r"((A)[3]), "r"(B0), "r"(B1))

__device__ __forceinline__ uint32_t packh2(float a, float b) {
    __half2 h = __floats2half2_rn(a, b);
    return *(uint32_t*)&h;
}

__global__ void __launch_bounds__(256, 2) gemm1_fused(const float* __restrict__ b1) {
    extern __shared__ char sm[];
    int tid = threadIdx.x;
    int m0 = blockIdx.x * 128, n0 = blockIdx.y * 128;

    // ---- copy A (pre-converted fp16, pure bulk copy) ----
    {
        const uint4* sA = (const uint4*)(g_Ah + (size_t)m0 * INF);
#pragma unroll
        for (int i = 0; i < 8; i++) {
            int idx = tid + i * 256;            // 0..2047 uint4
            int row = idx >> 4, c = idx & 15;
            *(uint4*)(sm + SA + row * 272 + c * 16) = sA[idx];
        }
    }
    // ---- copy B (W1^T) tile ----
    {
        int nn = tid >> 1, half = tid & 1;
        const uint4* sBg = (const uint4*)&g_Bh[(n0 + nn) * INF + half * 64];
        uint4* dB = (uint4*)(sm + SB + nn * 272 + half * 128);
#pragma unroll
        for (int i = 0; i < 8; i++) dB[i] = sBg[i];
    }
    // ---- copy W2^T ----
    {
        const uint4* sh = (const uint4*)g_W2h;
        uint4* dh = (uint4*)(sm + SW2);
#pragma unroll
        for (int i = 0; i < 7; i++) {
            int idx = tid + i * 256;
            if (idx < (W2N * W2LD * 2) / 16) dh[idx] = sh[idx];
        }
    }
    __syncthreads();

    int lane = tid & 31, w = tid >> 5;
    int wm = (w & 3) * 32, wn = (w >> 2) * 64;
    uint32_t sb = smem_u32(sm);

    uint32_t aRow = (uint32_t)(wm + (lane & 15));
    uint32_t aK   = (uint32_t)((lane >> 4) * 8);
    uint32_t aOff = sb + SA + aRow * 272 + aK * 2;
    uint32_t bRow = (uint32_t)(wn + (lane & 7) + ((lane >> 4) & 1) * 8);
    uint32_t bK   = (uint32_t)(((lane >> 3) & 1) * 8);
    uint32_t bOff = sb + SB + bRow * 272 + bK * 2;

    float acc[2][8][4];
#pragma unroll
    for (int a = 0; a < 2; a++)
#pragma unroll
        for (int b = 0; b < 8; b++)
#pragma unroll
            for (int c = 0; c < 4; c++) acc[a][b][c] = 0.f;

#pragma unroll
    for (int ks = 0; ks < 8; ks++) {
        uint32_t k2 = (uint32_t)(ks * 32);
        uint32_t Aa[2][4], Bb[4][4];
        LDSM4(Aa[0], aOff + k2);
        LDSM4(Aa[1], aOff + k2 + 16 * 272);
#pragma unroll
        for (int p = 0; p < 4; p++)
            LDSM4(Bb[p], bOff + k2 + p * 16 * 272);
#pragma unroll
        for (int mf = 0; mf < 2; mf++) {
#pragma unroll
            for (int nf = 0; nf < 8; nf++) {
                int p = nf >> 1, s = (nf & 1) * 2;
                MMAF16(acc[mf][nf], Aa[mf], Bb[p][s], Bb[p][s + 1]);
            }
        }
    }

    // ---- bias + relu in registers ----
    int t = lane & 3;
#pragma unroll
    for (int nf = 0; nf < 8; nf++) {
        int col = n0 + wn + nf * 8 + t * 2;
        float2 bb = *(const float2*)&b1[col];
#pragma unroll
        for (int mf = 0; mf < 2; mf++) {
            acc[mf][nf][0] = fmaxf(acc[mf][nf][0] + bb.x, 0.f);
            acc[mf][nf][1] = fmaxf(acc[mf][nf][1] + bb.y, 0.f);
            acc[mf][nf][2] = fmaxf(acc[mf][nf][2] + bb.x, 0.f);
            acc[mf][nf][3] = fmaxf(acc[mf][nf][3] + bb.y, 0.f);
        }
    }

    // ---- gemm2: z(fp16) @ W2, k-slice = warp's 64 cols ----
    float oacc[2][5][4];
#pragma unroll
    for (int a = 0; a < 2; a++)
#pragma unroll
        for (int b = 0; b < 5; b++)
#pragma unroll
            for (int c = 0; c < 4; c++) oacc[a][b][c] = 0.f;

    uint32_t w2row = (uint32_t)((lane & 7) + ((lane >> 4) & 1) * 8);
    uint32_t w2kh  = (uint32_t)(((lane >> 3) & 1) * 16);
    uint32_t w2base = sb + SW2 + w2row * (W2LD * 2) + w2kh;

#pragma unroll
    for (int c = 0; c < 4; c++) {
        uint32_t kb = (uint32_t)((n0 + wn + 16 * c) * 2);
        uint32_t Bq[3][4];
#pragma unroll
        for (int p = 0; p < 3; p++)
            LDSM4(Bq[p], w2base + p * 16 * (W2LD * 2) + kb);
#pragma unroll
        for (int mf = 0; mf < 2; mf++) {
            uint32_t za[4];
            za[0] = packh2(acc[mf][2 * c][0],     acc[mf][2 * c][1]);
            za[1] = packh2(acc[mf][2 * c][2],     acc[mf][2 * c][3]);
            za[2] = packh2(acc[mf][2 * c + 1][0], acc[mf][2 * c + 1][1]);
            za[3] = packh2(acc[mf][2 * c + 1][2], acc[mf][2 * c + 1][3]);
#pragma unroll
            for (int o = 0; o < 5; o++) {
                int p = o >> 1, s = (o & 1) * 2;
                MMAF16(oacc[mf][o], za, Bq[p][s], Bq[p][s + 1]);
            }
        }
    }

    // ---- write partials ----
    int bufid = blockIdx.y * 2 + (w >> 2);
    int g = lane >> 2;
    float* part = g_part[bufid];
#pragma unroll
    for (int mf = 0; mf < 2; mf++) {
        int r0 = m0 + wm + mf * 16 + g;
        int r1 = r0 + 8;
#pragma unroll
        for (int o = 0; o < 5; o++) {
            int col = o * 8 + t * 2;
            if (r0 < Nn) *(float2*)&part[(size_t)r0 * CLSF + col] =
                make_float2(oacc[mf][o][0], oacc[mf][o][1]);
            if (r1 < Nn) *(float2*)&part[(size_t)r1 * CLSF + col] =
                make_float2(oacc[mf][o][2], oacc[mf][o][3]);
        }
    }
}

// ---------------- combine: out = sum(parts) + b2 ----------------
__global__ void combine_k(const float* __restrict__ b2, float* __restrict__ out) {
    int i = blockIdx.x * 256 + threadIdx.x;      // float2 index
    if (i >= Nn * CLSF / 2) return;
    const float2* p0 = (const float2*)g_part[0];
    const float2* p1 = (const float2*)g_part[1];
    const float2* p2 = (const float2*)g_part[2];
    const float2* p3 = (const float2*)g_part[3];
    float2 a = p0[i], b = p1[i], c = p2[i], d = p3[i];
    int col2 = i % (CLSF / 2);
    float2 bb = *(const float2*)&b2[col2 * 2];
    float2 o;
    o.x = a.x + b.x + c.x + d.x + bb.x;
    o.y = a.y + b.y + c.y + d.y + bb.y;
    ((float2*)out)[i] = o;
}

extern "C" void kernel_launch(void* const* d_in, const int* in_sizes, int n_in,
                              void* d_out, int out_size) {
    const float* features = (const float*)d_in[0];
    const int*   src      = (const int*)d_in[1];
    const int*   dst      = (const int*)d_in[2];
    const float* W1       = (const float*)d_in[3];
    const float* b1       = (const float*)d_in[4];
    const float* W2       = (const float*)d_in[5];
    const float* b2       = (const float*)d_in[6];
    float*       out      = (float*)d_out;

    cudaFuncSetAttribute(gemm1_fused, cudaFuncAttributeMaxDynamicSharedMemorySize, SM_TOT);

    init_k<<<SBLK, 256>>>(W1, W2);
    hist_k<<<Ee / 1024, 256>>>((const int4*)dst);
    csr_k<<<SBLK, 256>>>((const float4*)features);
    permute_k<<<Ee / 1024, 256>>>((const int4*)src, (const int4*)dst);

    gather1_k<<<Nn / 8, 256>>>();
    gather2_k<<<Nn / 8, 256>>>();

    gemm1_fused<<<dim3(MTILES, 2), 256, SM_TOT>>>(b1);
    combine_k<<<(Nn * CLSF / 2 + 255) / 256, 256>>>(b2, out);
}

// round 16
// speedup vs baseline: 1.0430x; 1.0430x over previous
#include <cuda_runtime.h>
#include <cuda_fp16.h>
#include <cstdint>

#define Nn   40000
#define Ee   640000
#define INF  128
#define HIDF 256
#define CLSF 40
#define MTILES 313
#define MPAD  (MTILES * 128)     // 40064
#define SBLK  157                // ceil(40000/256)
#define EBLK  2500               // Ee/256
#define W2N   48                 // padded n for W2^T
#define W2LD  264                // padded k stride (528B rows)

// ---- scratch (device globals; zero-initialized at load) ----
__device__ int    g_deg[Nn];
__device__ int    g_row[Nn + 1];
__device__ int    g_cur[Nn];
__device__ int    g_esrc[Ee];
__device__ int    g_bsum[SBLK];
__device__ int    g_boff[SBLK];
__device__ int    g_tilec[MTILES];        // gemm tail-combine tickets (self-resetting)
__device__ float  g_norm[Nn];
__device__ float  g_norm2[Nn];
__device__ __align__(16) __half g_Xs[Nn * INF];             // norm.*X fp16
__device__ __align__(16) __half g_T[Nn * INF];              // norm2.*(A Xs) fp16
__device__ __align__(16) __half g_Ah[MPAD * INF];           // norm.*(A T) fp16, pad rows 0
__device__ __align__(16) unsigned short g_Bh[HIDF * INF];   // W1^T fp16, [n][k]
__device__ __align__(16) unsigned short g_W2h[W2N * W2LD];  // W2^T fp16
__device__ float  g_part[4][Nn * CLSF];                     // gemm2 partials

// ---------------- init: zero deg ----------------
__global__ void init_k() {
    int t = blockIdx.x * 256 + threadIdx.x;
    if (t < Nn) g_deg[t] = 0;
}

// ---- histogram: 1 edge/thread (max MLP) ----
__global__ void hist_k(const int* __restrict__ dst) {
    int i = blockIdx.x * 256 + threadIdx.x;
    if (i < Ee) atomicAdd(&g_deg[dst[i]], 1);
}

// ---- bsum (blocks < SBLK) + weight prep (extra blocks, independent) ----
__global__ void bsum_k(const float* __restrict__ W1, const float* __restrict__ W2) {
    int b = blockIdx.x;
    if (b < SBLK) {
        __shared__ int ws[8];
        int i = b * 256 + threadIdx.x;
        int v = (i < Nn) ? g_deg[i] : 0;
#pragma unroll
        for (int o = 16; o > 0; o >>= 1) v += __shfl_down_sync(0xffffffffu, v, o);
        int lane = threadIdx.x & 31, w = threadIdx.x >> 5;
        if (lane == 0) ws[w] = v;
        __syncthreads();
        if (w == 0) {
            int s = (lane < 8) ? ws[lane] : 0;
#pragma unroll
            for (int o = 4; o > 0; o >>= 1) s += __shfl_down_sync(0xffffffffu, s, o);
            if (lane == 0) g_bsum[b] = s;
        }
    } else {
        int t = (b - SBLK) * 256 + threadIdx.x;
        if (t < 8192) {                         // W1: n = t>>5, k0 = (t&31)*4
            int n = t >> 5, k0 = (t & 31) * 4;
            unsigned short h[4];
#pragma unroll
            for (int i = 0; i < 4; i++)
                h[i] = __half_as_ushort(__float2half_rn(W1[(k0 + i) * HIDF + n]));
            *(uint2*)&g_Bh[n * INF + k0] =
                make_uint2((uint32_t)h[1] << 16 | h[0], (uint32_t)h[3] << 16 | h[2]);
        } else if (t < 8192 + 2560) {           // W2
            int u = t - 8192;
            int n = u >> 6, k0 = (u & 63) * 4;
            unsigned short h[4];
#pragma unroll
            for (int i = 0; i < 4; i++)
                h[i] = __half_as_ushort(__float2half_rn(W2[(k0 + i) * CLSF + n]));
            *(uint2*)&g_W2h[n * W2LD + k0] =
                make_uint2((uint32_t)h[1] << 16 | h[0], (uint32_t)h[3] << 16 | h[2]);
        }
    }
}

__global__ void bscan_k() {
    __shared__ int ws[8];
    int t = threadIdx.x;
    int v = (t < SBLK) ? g_bsum[t] : 0;
    int lane = t & 31, w = t >> 5;
    int inc = v;
#pragma unroll
    for (int o = 1; o < 32; o <<= 1) {
        int n = __shfl_up_sync(0xffffffffu, inc, o);
        if (lane >= o) inc += n;
    }
    if (lane == 31) ws[w] = inc;
    __syncthreads();
    if (w == 0) {
        int s = (lane < 8) ? ws[lane] : 0;
        int si = s;
#pragma unroll
        for (int o = 1; o < 8; o <<= 1) {
            int n = __shfl_up_sync(0xffffffffu, si, o);
            if (lane >= o) si += n;
        }
        if (lane < 8) ws[lane] = si - s;
    }
    __syncthreads();
    if (t < SBLK) g_boff[t] = ws[w] + inc - v;
}

__global__ void fill_k() {
    __shared__ int ws[8];
    int i = blockIdx.x * 256 + threadIdx.x;
    int lane = threadIdx.x & 31, w = threadIdx.x >> 5;
    int d = (i < Nn) ? g_deg[i] : 0;
    int inc = d;
#pragma unroll
    for (int o = 1; o < 32; o <<= 1) {
        int n = __shfl_up_sync(0xffffffffu, inc, o);
        if (lane >= o) inc += n;
    }
    if (lane == 31) ws[w] = inc;
    __syncthreads();
    if (w == 0) {
        int s = (lane < 8) ? ws[lane] : 0;
        int si = s;
#pragma unroll
        for (int o = 1; o < 8; o <<= 1) {
            int n = __shfl_up_sync(0xffffffffu, si, o);
            if (lane >= o) si += n;
        }
        if (lane < 8) ws[lane] = si - s;
    }
    __syncthreads();
    if (i < Nn) {
        int off = g_boff[blockIdx.x] + ws[w] + inc - d;
        g_row[i] = off;
        g_cur[i] = off;
        float nm = rsqrtf(fmaxf((float)d, 1.0f));
        g_norm[i] = nm;
        g_norm2[i] = nm * nm;
    }
}

// ---- permute (blocks < EBLK, 1 edge/thread) + prepX (extra 5000 blocks) ----
__global__ void scatter_k(const int* __restrict__ src, const int* __restrict__ dst,
                          const float4* __restrict__ xin) {
    int b = blockIdx.x;
    if (b < EBLK) {
        int i = b * 256 + threadIdx.x;
        int d = dst[i];
        int p = atomicAdd(&g_cur[d], 1);
        g_esrc[p] = src[i];
    } else {
        int node = (b - EBLK) * 8 + (threadIdx.x >> 5);
        int lane = threadIdx.x & 31;
        if (node < Nn) {
            float nm = g_norm[node];
            float4 x = xin[node * 32 + lane];
            __half2 p0 = __floats2half2_rn(x.x * nm, x.y * nm);
            __half2 p1 = __floats2half2_rn(x.z * nm, x.w * nm);
            uint2 pk;
            pk.x = *(uint32_t*)&p0;
            pk.y = *(uint32_t*)&p1;
            ((uint2*)g_Xs)[node * 32 + lane] = pk;
        }
    }
}

// ---- hop1: T[v] = norm2[v] * sum Xs[src] ----
__global__ void gather1_k() {
    int w = (blockIdx.x * blockDim.x + threadIdx.x) >> 5;
    int lane = threadIdx.x & 31;
    if (w >= Nn) return;
    int beg = g_row[w], end = beg + g_deg[w];
    const uint2* rows = (const uint2*)g_Xs;
    float a0 = 0.f, a1 = 0.f, a2 = 0.f, a3 = 0.f;
    int e = beg;
    for (; e + 3 < end; e += 4) {
        int s0 = g_esrc[e], s1 = g_esrc[e + 1], s2 = g_esrc[e + 2], s3 = g_esrc[e + 3];
        uint2 p0 = rows[s0 * 32 + lane], p1 = rows[s1 * 32 + lane];
        uint2 p2 = rows[s2 * 32 + lane], p3 = rows[s3 * 32 + lane];
        float2 f;
        f = __half22float2(*(__half2*)&p0.x); a0 += f.x; a1 += f.y;
        f = __half22float2(*(__half2*)&p0.y); a2 += f.x; a3 += f.y;
        f = __half22float2(*(__half2*)&p1.x); a0 += f.x; a1 += f.y;
        f = __half22float2(*(__half2*)&p1.y); a2 += f.x; a3 += f.y;
        f = __half22float2(*(__half2*)&p2.x); a0 += f.x; a1 += f.y;
        f = __half22float2(*(__half2*)&p2.y); a2 += f.x; a3 += f.y;
        f = __half22float2(*(__half2*)&p3.x); a0 += f.x; a1 += f.y;
        f = __half22float2(*(__half2*)&p3.y); a2 += f.x; a3 += f.y;
    }
    for (; e < end; e++) {
        int s0 = g_esrc[e];
        uint2 p0 = rows[s0 * 32 + lane];
        float2 f;
        f = __half22float2(*(__half2*)&p0.x); a0 += f.x; a1 += f.y;
        f = __half22float2(*(__half2*)&p0.y); a2 += f.x; a3 += f.y;
    }
    float n2 = g_norm2[w];
    __half2 q0 = __floats2half2_rn(a0 * n2, a1 * n2);
    __half2 q1 = __floats2half2_rn(a2 * n2, a3 * n2);
    uint2 o;
    o.x = *(uint32_t*)&q0;
    o.y = *(uint32_t*)&q1;
    ((uint2*)g_T)[w * 32 + lane] = o;
}

// ---- hop2: Ah[v] = norm[v] * sum T[src] ----
__global__ void gather2_k() {
    int w = (blockIdx.x * blockDim.x + threadIdx.x) >> 5;
    int lane = threadIdx.x & 31;
    if (w >= Nn) return;
    int beg = g_row[w], end = beg + g_deg[w];
    const uint2* rows = (const uint2*)g_T;
    float a0 = 0.f, a1 = 0.f, a2 = 0.f, a3 = 0.f;
    int e = beg;
    for (; e + 3 < end; e += 4) {
        int s0 = g_esrc[e], s1 = g_esrc[e + 1], s2 = g_esrc[e + 2], s3 = g_esrc[e + 3];
        uint2 p0 = rows[s0 * 32 + lane], p1 = rows[s1 * 32 + lane];
        uint2 p2 = rows[s2 * 32 + lane], p3 = rows[s3 * 32 + lane];
        float2 f;
        f = __half22float2(*(__half2*)&p0.x); a0 += f.x; a1 += f.y;
        f = __half22float2(*(__half2*)&p0.y); a2 += f.x; a3 += f.y;
        f = __half22float2(*(__half2*)&p1.x); a0 += f.x; a1 += f.y;
        f = __half22float2(*(__half2*)&p1.y); a2 += f.x; a3 += f.y;
        f = __half22float2(*(__half2*)&p2.x); a0 += f.x; a1 += f.y;
        f = __half22float2(*(__half2*)&p2.y); a2 += f.x; a3 += f.y;
        f = __half22float2(*(__half2*)&p3.x); a0 += f.x; a1 += f.y;
        f = __half22float2(*(__half2*)&p3.y); a2 += f.x; a3 += f.y;
    }
    for (; e < end; e++) {
        int s0 = g_esrc[e];
        uint2 p0 = rows[s0 * 32 + lane];
        float2 f;
        f = __half22float2(*(__half2*)&p0.x); a0 += f.x; a1 += f.y;
        f = __half22float2(*(__half2*)&p0.y); a2 += f.x; a3 += f.y;
    }
    float nw = g_norm[w];
    __half2 q0 = __floats2half2_rn(a0 * nw, a1 * nw);
    __half2 q1 = __floats2half2_rn(a2 * nw, a3 * nw);
    uint2 o;
    o.x = *(uint32_t*)&q0;
    o.y = *(uint32_t*)&q1;
    ((uint2*)g_Ah)[w * 32 + lane] = o;
}

// ---------------- fused GEMM1+GEMM2 via fp16 mma.sync + tail combine ----------------
#define SA   0                   // 128 x 272B = 34816
#define SB   34816               // 128 x 272B = 34816
#define SW2  69632               // 48*264*2 = 25344
#define SM_TOT 94976

__device__ __forceinline__ uint32_t smem_u32(const void* p) {
    uint32_t a;
    asm("{ .reg .u64 t; cvta.to.shared.u64 t, %1; cvt.u32.u64 %0, t; }" : "=r"(a) : "l"(p));
    return a;
}
#define LDSM4(R, addr) \
    asm volatile("ldmatrix.sync.aligned.m8n8.x4.shared.b16 {%0,%1,%2,%3}, [%4];" \
        : "=r"((R)[0]), "=r"((R)[1]), "=r"((R)[2]), "=r"((R)[3]) : "r"(addr))
#define MMAF16(C, A, B0, B1) \
    asm volatile("mma.sync.aligned.m16n8k16.row.col.f32.f16.f16.f32 " \
        "{%0,%1,%2,%3},{%4,%5,%6,%7},{%8,%9},{%0,%1,%2,%3};" \
        : "+f"((C)[0]), "+f"((C)[1]), "+f"((C)[2]), "+f"((C)[3]) \
        : "r"((A)[0]), "r"((A)[1]), "r"((A)[2]), "r"((A)[3]), "r"(B0), "r"(B1))

__device__ __forceinline__ uint32_t packh2(float a, float b) {
    __half2 h = __floats2half2_rn(a, b);
    return *(uint32_t*)&h;
}

__global__ void __launch_bounds__(256, 2) gemm1_fused(const float* __restrict__ b1,
                                                      const float* __restrict__ b2,
                                                      float* __restrict__ out) {
    extern __shared__ char sm[];
    __shared__ int s_last;
    int tid = threadIdx.x;
    int m0 = blockIdx.x * 128, n0 = blockIdx.y * 128;

    // ---- copy A (pre-converted fp16, pure bulk copy) ----
    {
        const uint4* sA = (const uint4*)(g_Ah + (size_t)m0 * INF);
#pragma unroll
        for (int i = 0; i < 8; i++) {
            int idx = tid + i * 256;            // 0..2047 uint4
            int row = idx >> 4, c = idx & 15;
            *(uint4*)(sm + SA + row * 272 + c * 16) = sA[idx];
        }
    }
    // ---- copy B (W1^T) tile ----
    {
        int nn = tid >> 1, half = tid & 1;
        const uint4* sBg = (const uint4*)&g_Bh[(n0 + nn) * INF + half * 64];
        uint4* dB = (uint4*)(sm + SB + nn * 272 + half * 128);
#pragma unroll
        for (int i = 0; i < 8; i++) dB[i] = sBg[i];
    }
    // ---- copy W2^T ----
    {
        const uint4* sh = (const uint4*)g_W2h;
        uint4* dh = (uint4*)(sm + SW2);
#pragma unroll
        for (int i = 0; i < 7; i++) {
            int idx = tid + i * 256;
            if (idx < (W2N * W2LD * 2) / 16) dh[idx] = sh[idx];
        }
    }
    __syncthreads();

    int lane = tid & 31, w = tid >> 5;
    int wm = (w & 3) * 32, wn = (w >> 2) * 64;
    uint32_t sb = smem_u32(sm);

    uint32_t aRow = (uint32_t)(wm + (lane & 15));
    uint32_t aK   = (uint32_t)((lane >> 4) * 8);
    uint32_t aOff = sb + SA + aRow * 272 + aK * 2;
    uint32_t bRow = (uint32_t)(wn + (lane & 7) + ((lane >> 4) & 1) * 8);
    uint32_t bK   = (uint32_t)(((lane >> 3) & 1) * 8);
    uint32_t bOff = sb + SB + bRow * 272 + bK * 2;

    float acc[2][8][4];
#pragma unroll
    for (int a = 0; a < 2; a++)
#pragma unroll
        for (int b = 0; b < 8; b++)
#pragma unroll
            for (int c = 0; c < 4; c++) acc[a][b][c] = 0.f;

#pragma unroll
    for (int ks = 0; ks < 8; ks++) {
        uint32_t k2 = (uint32_t)(ks * 32);
        uint32_t Aa[2][4], Bb[4][4];
        LDSM4(Aa[0], aOff + k2);
        LDSM4(Aa[1], aOff + k2 + 16 * 272);
#pragma unroll
        for (int p = 0; p < 4; p++)
            LDSM4(Bb[p], bOff + k2 + p * 16 * 272);
#pragma unroll
        for (int mf = 0; mf < 2; mf++) {
#pragma unroll
            for (int nf = 0; nf < 8; nf++) {
                int p = nf >> 1, s = (nf & 1) * 2;
                MMAF16(acc[mf][nf], Aa[mf], Bb[p][s], Bb[p][s + 1]);
            }
        }
    }

    // ---- bias + relu in registers ----
    int t = lane & 3;
#pragma unroll
    for (int nf = 0; nf < 8; nf++) {
        int col = n0 + wn + nf * 8 + t * 2;
        float2 bb = *(const float2*)&b1[col];
#pragma unroll
        for (int mf = 0; mf < 2; mf++) {
            acc[mf][nf][0] = fmaxf(acc[mf][nf][0] + bb.x, 0.f);
            acc[mf][nf][1] = fmaxf(acc[mf][nf][1] + bb.y, 0.f);
            acc[mf][nf][2] = fmaxf(acc[mf][nf][2] + bb.x, 0.f);
            acc[mf][nf][3] = fmaxf(acc[mf][nf][3] + bb.y, 0.f);
        }
    }

    // ---- gemm2: z(fp16) @ W2, k-slice = warp's 64 cols ----
    float oacc[2][5][4];
#pragma unroll
    for (int a = 0; a < 2; a++)
#pragma unroll
        for (int b = 0; b < 5; b++)
#pragma unroll
            for (int c = 0; c < 4; c++) oacc[a][b][c] = 0.f;

    uint32_t w2row = (uint32_t)((lane & 7) + ((lane >> 4) & 1) * 8);
    uint32_t w2kh  = (uint32_t)(((lane >> 3) & 1) * 16);
    uint32_t w2base = sb + SW2 + w2row * (W2LD * 2) + w2kh;

#pragma unroll
    for (int c = 0; c < 4; c++) {
        uint32_t kb = (uint32_t)((n0 + wn + 16 * c) * 2);
        uint32_t Bq[3][4];
#pragma unroll
        for (int p = 0; p < 3; p++)
            LDSM4(Bq[p], w2base + p * 16 * (W2LD * 2) + kb);
#pragma unroll
        for (int mf = 0; mf < 2; mf++) {
            uint32_t za[4];
            za[0] = packh2(acc[mf][2 * c][0],     acc[mf][2 * c][1]);
            za[1] = packh2(acc[mf][2 * c][2],     acc[mf][2 * c][3]);
            za[2] = packh2(acc[mf][2 * c + 1][0], acc[mf][2 * c + 1][1]);
            za[3] = packh2(acc[mf][2 * c + 1][2], acc[mf][2 * c + 1][3]);
#pragma unroll
            for (int o = 0; o < 5; o++) {
                int p = o >> 1, s = (o & 1) * 2;
                MMAF16(oacc[mf][o], za, Bq[p][s], Bq[p][s + 1]);
            }
        }
    }

    // ---- write partials ----
    int bufid = blockIdx.y * 2 + (w >> 2);
    int g = lane >> 2;
    float* part = g_part[bufid];
#pragma unroll
    for (int mf = 0; mf < 2; mf++) {
        int r0 = m0 + wm + mf * 16 + g;
        int r1 = r0 + 8;
#pragma unroll
        for (int o = 0; o < 5; o++) {
            int col = o * 8 + t * 2;
            if (r0 < Nn) *(float2*)&part[(size_t)r0 * CLSF + col] =
                make_float2(oacc[mf][o][0], oacc[mf][o][1]);
            if (r1 < Nn) *(float2*)&part[(size_t)r1 * CLSF + col] =
                make_float2(oacc[mf][o][2], oacc[mf][o][3]);
        }
    }

    // ---- tail combine: 2nd-arriving y-CTA of this m-tile sums partials ----
    __threadfence();
    __syncthreads();
    if (tid == 0) s_last = atomicAdd(&g_tilec[blockIdx.x], 1);
    __syncthreads();
    if (s_last == 1) {
        __threadfence();   // acquire side: order partial reads after ticket
        const float2* p0 = (const float2*)g_part[0];
        const float2* p1 = (const float2*)g_part[1];
        const float2* p2 = (const float2*)g_part[2];
        const float2* p3 = (const float2*)g_part[3];
        int base2 = m0 * (CLSF / 2);            // float2 index of row m0
#pragma unroll
        for (int it = 0; it < 10; it++) {
            int i = tid + it * 256;             // 0..2559
            int row = m0 + i / (CLSF / 2);
            if (row < Nn) {
                int idx = base2 + i;
                float2 a = p0[idx], b = p1[idx], c = p2[idx], d = p3[idx];
                float2 bb = *(const float2*)&b2[(i % (CLSF / 2)) * 2];
                float2 o;
                o.x = a.x + b.x + c.x + d.x + bb.x;
                o.y = a.y + b.y + c.y + d.y + bb.y;
                ((float2*)out)[idx] = o;
            }
        }
        if (tid == 0) g_tilec[blockIdx.x] = 0;  // reset for next graph replay
    }
}

extern "C" void kernel_launch(void* const* d_in, const int* in_sizes, int n_in,
                              void* d_out, int out_size) {
    const float* features = (const float*)d_in[0];
    const int*   src      = (const int*)d_in[1];
    const int*   dst      = (const int*)d_in[2];
    const float* W1       = (const float*)d_in[3];
    const float* b1       = (const float*)d_in[4];
    const float* W2       = (const float*)d_in[5];
    const float* b2       = (const float*)d_in[6];
    float*       out      = (float*)d_out;

    cudaFuncSetAttribute(gemm1_fused, cudaFuncAttributeMaxDynamicSharedMemorySize, SM_TOT);

    init_k<<<SBLK, 256>>>();
    hist_k<<<EBLK, 256>>>(dst);
    bsum_k<<<SBLK + 42, 256>>>(W1, W2);
    bscan_k<<<1, 256>>>();
    fill_k<<<SBLK, 256>>>();
    scatter_k<<<EBLK + 5000, 256>>>(src, dst, (const float4*)features);

    gather1_k<<<Nn / 8, 256>>>();
    gather2_k<<<Nn / 8, 256>>>();

    gemm1_fused<<<dim3(MTILES, 2), 256, SM_TOT>>>(b1, b2, out);
}